// round 16
// baseline (speedup 1.0000x reference)
#include <cuda_runtime.h>
#include <cuda_fp16.h>
#include <cstdint>
#include <cstddef>

#define K_DIM  4096
#define M_ROWS 8192
#define N_DIM  4096
#define KQ_DIM 3968            // exact-fp16 integer-weight part
#define N_OUTL 128

// GEMM tiling: 256x128 CTA tile, warp-specialized 8 consumer + 2 producer warps
#define TM 256
#define TN 128
#define KC 64
#define NT (K_DIM / KC)        // 64 k-iterations
#define NQ_IT (KQ_DIM / KC)    // 62 q-part iterations
#define STAGES 4
#define NTHREADS 320           // 256 consumers + 64 producers

// Stage smem layout (bytes): A 256x64 fp16 = 32K, B 128x64 fp16 = 16K
#define OFF_A 0
#define OFF_B (32 * 1024)
#define STAGE_BYTES (48 * 1024)
#define SM_STG 1024            // stages start after barrier block
#define SMEM_TOTAL (SM_STG + STAGES * STAGE_BYTES)   // 197632

// fused prep kernel split point
#define GATHER_BLOCKS (M_ROWS * (K_DIM / 2) / 256)     // 65536
#define W_BLOCKS      ((N_DIM * K_DIM / 4) / 256)      // 16384

// ---------------------------------------------------------------------------
// Device-global scratch (no runtime allocation)
// ---------------------------------------------------------------------------
__device__ __half g_A [(size_t)M_ROWS * K_DIM];    // permuted x, fp16
__device__ __half g_Q [(size_t)N_DIM * KQ_DIM];    // exact fp16 int weights
__device__ __half g_FP[(size_t)N_DIM * N_OUTL];    // fp16 outlier weights
__device__ int    g_cp[K_DIM];                     // forward column perm

// ---------------------------------------------------------------------------
// Base-target PTX helpers (mbarrier/cp.async/ldmatrix/mma: all compile at
// compute_103 base — verified via R3 ptxas log)
// ---------------------------------------------------------------------------
__device__ __forceinline__ uint32_t smem_to_u32(const void* p) {
    uint32_t a;
    asm("{ .reg .u64 t; cvta.to.shared.u64 t, %1; cvt.u32.u64 %0, t; }"
        : "=r"(a) : "l"(p));
    return a;
}

__device__ __forceinline__ void cpa16(uint32_t dst, const void* src) {
    asm volatile("cp.async.cg.shared.global [%0], [%1], 16;"
                 :: "r"(dst), "l"(src) : "memory");
}

__device__ __forceinline__ void ldsm4(uint32_t* r, uint32_t addr) {
    asm volatile("ldmatrix.sync.aligned.m8n8.x4.shared.b16 {%0,%1,%2,%3}, [%4];"
                 : "=r"(r[0]), "=r"(r[1]), "=r"(r[2]), "=r"(r[3]) : "r"(addr));
}

__device__ __forceinline__ void mma16816(float* c, const uint32_t* a,
                                         uint32_t b0, uint32_t b1) {
    asm volatile(
        "mma.sync.aligned.m16n8k16.row.col.f32.f16.f16.f32 "
        "{%0,%1,%2,%3}, {%4,%5,%6,%7}, {%8,%9}, {%0,%1,%2,%3};"
        : "+f"(c[0]), "+f"(c[1]), "+f"(c[2]), "+f"(c[3])
        : "r"(a[0]), "r"(a[1]), "r"(a[2]), "r"(a[3]), "r"(b0), "r"(b1));
}

#define MBARRIER_INIT(addr, cnt) \
    asm volatile("mbarrier.init.shared.b64 [%0], %1;" \
                 :: "r"((uint32_t)(addr)), "r"((uint32_t)(cnt)) : "memory")

#define MBARRIER_ARRIVE(addr) \
    asm volatile("mbarrier.arrive.shared.b64 _, [%0];" \
                 :: "r"((uint32_t)(addr)) : "memory")

#define MBARRIER_WAIT_PARITY(mbar_smem_addr, phase_parity) do { \
    uint32_t _mbar = (uint32_t)(mbar_smem_addr); \
    uint32_t _parity = (uint32_t)(phase_parity); \
    uint32_t _done; \
    asm volatile( \
        "{\n\t.reg .pred p;\n\t" \
        "mbarrier.try_wait.parity.acquire.cta.shared::cta.b64 p, [%1], %2;\n\t" \
        "selp.b32 %0, 1, 0, p;\n\t}" \
        : "=r"(_done) : "r"(_mbar), "r"(_parity) : "memory"); \
    if (!_done) { \
        asm volatile( \
            "{\n\t.reg .pred P1;\n\t" \
            "WAIT_LOOP_%=:\n\t" \
            "mbarrier.try_wait.parity.acquire.cta.shared::cta.b64 P1, [%0], %1, 0x989680;\n\t" \
            "@P1 bra.uni WAIT_DONE_%=;\n\t" \
            "bra.uni WAIT_LOOP_%=;\n\t" \
            "WAIT_DONE_%=:\n\t}" \
            :: "r"(_mbar), "r"(_parity) : "memory"); \
    } \
} while (0)

// barrier layout: full[s] @ sbase + s*16, empty[s] @ sbase + s*16 + 8
#define FULL_BAR(sb, s)  ((sb) + (uint32_t)(s) * 16)
#define EMPTY_BAR(sb, s) ((sb) + (uint32_t)(s) * 16 + 8)

// 128B-row tile, 8 granules of 16B, XOR-swizzled (verified conflict-free).
__device__ __forceinline__ uint32_t tile_off(int row, int g) {
    return (uint32_t)(row * 128 + ((g ^ (row & 7)) * 16));
}

// ---------------------------------------------------------------------------
// Prep pass 0: forward permutation cp[invp[c]] = c  (xp[j] = x[cp[j]]).
// ---------------------------------------------------------------------------
__global__ void build_cp_kernel(const int* __restrict__ invp) {
    int j = blockIdx.x * 256 + threadIdx.x;
    g_cp[invp[j]] = j;
}

// Prep pass 1 (fused): A-gather+convert blocks, then W-convert blocks.
__global__ __launch_bounds__(256)
void prep_AW_kernel(const float* __restrict__ x,
                    const float4* __restrict__ qw4,
                    const float4* __restrict__ fw4) {
    const int b = blockIdx.x;
    if (b < GATHER_BLOCKS) {
        size_t idx = (size_t)b * 256 + threadIdx.x;        // over M*K/2
        const int m  = (int)(idx >> 11);                   // K/2 = 2048
        const int j2 = (int)(idx & 2047);
        const float* xr = x + (size_t)m * K_DIM;
        const int c0 = g_cp[2 * j2], c1 = g_cp[2 * j2 + 1];
        ((__half2*)(g_A + (size_t)m * K_DIM))[j2] =
            __floats2half2_rn(xr[c0], xr[c1]);
    } else {
        size_t idx = (size_t)(b - GATHER_BLOCKS) * 256 + threadIdx.x;
        const size_t nq4 = (size_t)N_DIM * KQ_DIM / 4;
        float4 v;
        __half2* dst;
        if (idx < nq4) { v = qw4[idx]; dst = (__half2*)(g_Q + 4 * idx); }
        else { v = fw4[idx - nq4]; dst = (__half2*)(g_FP + 4 * (idx - nq4)); }
        dst[0] = __floats2half2_rn(v.x, v.y);
        dst[1] = __floats2half2_rn(v.z, v.w);
    }
}

// ---------------------------------------------------------------------------
// GEMM: acc = xp[:, :3968]*q^T ; acc *= alpha[n] ; acc += outliers ; +bias.
// Warp-specialized: warps 0-7 consume (64x64 tiles on 256x128 CTA tile),
// warps 8-9 produce via cp.async. mbarrier full/empty ring, 4 stages.
// Consumers never issue cp.async and never hit a CTA-wide barrier.
// ---------------------------------------------------------------------------
__global__ __launch_bounds__(NTHREADS, 1)
void gemm_hmma_kernel(const float* __restrict__ alpha,
                      const float* __restrict__ bias,
                      float* __restrict__ C) {
    extern __shared__ char smem[];
    const uint32_t sbase = smem_to_u32(smem);
    const uint32_t stg0  = sbase + SM_STG;
    const int tid = threadIdx.x;
    const int wid = tid >> 5;
    const int lid = tid & 31;
    const int m0  = blockIdx.y * TM;
    const int n0  = blockIdx.x * TN;

    if (tid == 0) {
        #pragma unroll
        for (int s = 0; s < STAGES; s++) {
            MBARRIER_INIT(FULL_BAR(sbase, s), 64);    // producer threads
            MBARRIER_INIT(EMPTY_BAR(sbase, s), 256);  // consumer threads
        }
    }
    __syncthreads();

    if (wid >= 8) {
        // ================= PRODUCER (warps 8,9; 64 threads) =================
        const int ptid = tid - 256;         // 0..63
        const int prow = ptid >> 3;         // 0..7
        const int pg   = ptid & 7;          // granule
        const __half* pA = g_A  + (size_t)(m0 + prow) * K_DIM  + pg * 8;
        const __half* pQ = g_Q  + (size_t)(n0 + prow) * KQ_DIM + pg * 8;
        const __half* pF = g_FP + (size_t)(n0 + prow) * N_OUTL + pg * 8;
        // swizzle term constant per thread (prow < 8 so row&7 == prow)
        const uint32_t dA = stg0 + OFF_A + (uint32_t)(prow * 128 + ((pg ^ prow) * 16));
        const uint32_t dB = stg0 + OFF_B + (uint32_t)(prow * 128 + ((pg ^ prow) * 16));

        int st = 0, ph = 1;                 // empty-wait cursor (phase 1 first)
        int at = 0;                         // full-arrive cursor (stage kt-3)
        #pragma unroll 1
        for (int kt = 0; kt < NT; kt++) {
            MBARRIER_WAIT_PARITY(EMPTY_BAR(sbase, st), ph);
            const uint32_t so = (uint32_t)st * STAGE_BYTES;
            #pragma unroll
            for (int p = 0; p < 32; p++)    // A: 256 rows, stride 8
                cpa16(dA + so + p * 1024u, pA + (size_t)p * (8 * K_DIM));
            pA += KC;
            if (kt < NQ_IT) {
                #pragma unroll
                for (int p = 0; p < 16; p++)  // B: exact int weights
                    cpa16(dB + so + p * 1024u, pQ + (size_t)p * (8 * KQ_DIM));
                pQ += KC;
            } else {
                const __half* f = pF + (size_t)(kt - NQ_IT) * KC;
                #pragma unroll
                for (int p = 0; p < 16; p++)  // B: fp outlier weights
                    cpa16(dB + so + p * 1024u, f + (size_t)p * (8 * N_OUTL));
            }
            asm volatile("cp.async.commit_group;" ::: "memory");
            if (kt >= 3) {
                asm volatile("cp.async.wait_group 3;" ::: "memory");
                MBARRIER_ARRIVE(FULL_BAR(sbase, at));
                at++; if (at == STAGES) at = 0;
            }
            st++; if (st == STAGES) { st = 0; ph ^= 1; }
        }
        // tail: signal the last 3 stages as their groups complete
        asm volatile("cp.async.wait_group 2;" ::: "memory");
        MBARRIER_ARRIVE(FULL_BAR(sbase, at));
        at++; if (at == STAGES) at = 0;
        asm volatile("cp.async.wait_group 1;" ::: "memory");
        MBARRIER_ARRIVE(FULL_BAR(sbase, at));
        at++; if (at == STAGES) at = 0;
        asm volatile("cp.async.wait_group 0;" ::: "memory");
        MBARRIER_ARRIVE(FULL_BAR(sbase, at));
        return;
    }

    // ================== CONSUMER (warps 0-7; 256 threads) ==================
    const int wm = wid >> 1;               // 0..3 -> m offset wm*64
    const int wn = wid & 1;                // 0..1 -> n offset wn*64

    float acc[4][8][4];                    // 128 regs
    #pragma unroll
    for (int i = 0; i < 4; i++)
        #pragma unroll
        for (int j = 0; j < 8; j++)
            #pragma unroll
            for (int t = 0; t < 4; t++) acc[i][j][t] = 0.0f;

    const int frow = lid & 15;
    const int fg   = lid >> 4;
    const uint32_t r7 = (uint32_t)(frow & 7);
    uint32_t aoff[4], boff[4];
    #pragma unroll
    for (int i = 0; i < 4; i++)
        aoff[i] = stg0 + OFF_A + (uint32_t)(wm * 64 + i * 16 + frow) * 128;
    #pragma unroll
    for (int j = 0; j < 4; j++)
        boff[j] = stg0 + OFF_B + (uint32_t)(wn * 64 + j * 16 + frow) * 128;

    // per stage: 4 k16 s-steps; per s-step 8 LDSM + 32 independent MMAs
    auto compute_stage = [&](uint32_t so) {
        #pragma unroll
        for (int s = 0; s < 4; s++) {
            const uint32_t sw = so + ((((uint32_t)(2 * s + fg)) ^ r7) << 4);
            uint32_t a[4][4], b[4][4];
            #pragma unroll
            for (int j = 0; j < 4; j++) ldsm4(b[j], boff[j] + sw);
            #pragma unroll
            for (int i = 0; i < 4; i++) ldsm4(a[i], aoff[i] + sw);
            #pragma unroll
            for (int i = 0; i < 4; i++)
                #pragma unroll
                for (int j = 0; j < 4; j++) {
                    mma16816(acc[i][2 * j],     a[i], b[j][0], b[j][2]);
                    mma16816(acc[i][2 * j + 1], a[i], b[j][1], b[j][3]);
                }
        }
    };

    const int tq = lid & 3;

#define CONS_ITER(SLOT, PH) do { \
        MBARRIER_WAIT_PARITY(FULL_BAR(sbase, SLOT), PH);    \
        compute_stage((uint32_t)(SLOT) * STAGE_BYTES);      \
        MBARRIER_ARRIVE(EMPTY_BAR(sbase, SLOT));            \
    } while (0)

    // 60 q-iterations in 15 full cycles (phase = cycle & 1)
    int ph = 0;
    #pragma unroll 1
    for (int c = 0; c < 15; c++) {
        CONS_ITER(0, ph); CONS_ITER(1, ph); CONS_ITER(2, ph); CONS_ITER(3, ph);
        ph ^= 1;
    }
    // q-iterations 60,61 (cycle 15, slots 0,1, phase 1)
    CONS_ITER(0, ph); CONS_ITER(1, ph);

    // ---- q-part complete: per-output-column alpha on accumulators ----
    #pragma unroll
    for (int j2 = 0; j2 < 8; j2++) {
        const int nc = n0 + wn * 64 + j2 * 8 + 2 * tq;
        const float s0 = alpha[nc], s1 = alpha[nc + 1];
        #pragma unroll
        for (int i = 0; i < 4; i++) {
            acc[i][j2][0] *= s0; acc[i][j2][1] *= s1;
            acc[i][j2][2] *= s0; acc[i][j2][3] *= s1;
        }
    }

    // outlier iterations 62,63 (cycle 15, slots 2,3, phase 1)
    CONS_ITER(2, ph); CONS_ITER(3, ph);
#undef CONS_ITER

    // ---- epilogue: bias + float2 stores ----
    const int qid = lid >> 2;
    #pragma unroll
    for (int i = 0; i < 4; i++) {
        const int mrow = m0 + wm * 64 + i * 16 + qid;
        #pragma unroll
        for (int j2 = 0; j2 < 8; j2++) {
            const int nc = n0 + wn * 64 + j2 * 8 + 2 * tq;
            const float b0 = bias[nc], b1 = bias[nc + 1];
            float2 v0 = make_float2(acc[i][j2][0] + b0, acc[i][j2][1] + b1);
            float2 v1 = make_float2(acc[i][j2][2] + b0, acc[i][j2][3] + b1);
            *(float2*)&C[(size_t)mrow * N_DIM + nc]       = v0;
            *(float2*)&C[(size_t)(mrow + 8) * N_DIM + nc] = v1;
        }
    }
}

// ---------------------------------------------------------------------------
// Launch. Inputs: input, q_weight, fp_weight, alpha_scale, bias, inv_col_perm.
// ---------------------------------------------------------------------------
extern "C" void kernel_launch(void* const* d_in, const int* in_sizes, int n_in,
                              void* d_out, int out_size) {
    const float* input = (const float*)d_in[0];
    const float* qw    = (const float*)d_in[1];
    const float* fw    = (const float*)d_in[2];
    const float* alpha = (const float*)d_in[3];
    const float* bias  = (const float*)d_in[4];
    const int*   invp  = (const int*)  d_in[5];
    float* out = (float*)d_out;

    build_cp_kernel<<<K_DIM / 256, 256>>>(invp);
    prep_AW_kernel<<<GATHER_BLOCKS + W_BLOCKS, 256>>>(
        input, (const float4*)qw, (const float4*)fw);

    static bool attr_set = false;
    if (!attr_set) {
        cudaFuncSetAttribute(gemm_hmma_kernel,
                             cudaFuncAttributeMaxDynamicSharedMemorySize, SMEM_TOTAL);
        attr_set = true;
    }
    dim3 grid(N_DIM / TN, M_ROWS / TM);   // (32, 32) = 1024 CTAs
    gemm_hmma_kernel<<<grid, NTHREADS, SMEM_TOTAL>>>(alpha, bias, out);
}

// round 17
// speedup vs baseline: 1.2109x; 1.2109x over previous
#include <cuda_runtime.h>
#include <cuda_fp16.h>
#include <cstdint>
#include <cstddef>

#define K_DIM  4096
#define M_ROWS 8192
#define N_DIM  4096
#define KQ_DIM 3968            // exact-fp16 integer-weight part
#define N_OUTL 128

// GEMM tiling: 128x128 CTA tile, 256 threads, 2 CTAs/SM (R13/R15 shape)
#define TM 128
#define TN 128
#define KC 64
#define NT (K_DIM / KC)        // 64 k-iterations
#define NQ_IT (KQ_DIM / KC)    // 62 q-part iterations
#define STAGES 3

// Stage smem layout (bytes): A 128x64 fp16 = 16K, B 128x64 fp16 = 16K
#define OFF_A 0
#define OFF_B (16 * 1024)
#define STAGE_BYTES (32 * 1024)
#define SMEM_TOTAL (STAGES * STAGE_BYTES)   // 98304 (2 CTAs -> 192K/SM)

// fused prep kernel split point (A blocks now over float4s of x)
#define GATHER_BLOCKS (M_ROWS * (K_DIM / 4) / 256)     // 32768
#define W_BLOCKS      ((N_DIM * K_DIM / 4) / 256)      // 16384

// ---------------------------------------------------------------------------
// Device-global scratch (no runtime allocation)
// ---------------------------------------------------------------------------
__device__ __half g_A [(size_t)M_ROWS * K_DIM];    // permuted x, fp16
__device__ __half g_Q [(size_t)N_DIM * KQ_DIM];    // exact fp16 int weights
__device__ __half g_FP[(size_t)N_DIM * N_OUTL];    // fp16 outlier weights

// ---------------------------------------------------------------------------
// Base-target PTX helpers
// ---------------------------------------------------------------------------
__device__ __forceinline__ uint32_t smem_to_u32(const void* p) {
    uint32_t a;
    asm("{ .reg .u64 t; cvta.to.shared.u64 t, %1; cvt.u32.u64 %0, t; }"
        : "=r"(a) : "l"(p));
    return a;
}

__device__ __forceinline__ void cpa16(uint32_t dst, const void* src) {
    asm volatile("cp.async.cg.shared.global [%0], [%1], 16;"
                 :: "r"(dst), "l"(src) : "memory");
}

__device__ __forceinline__ void ldsm4(uint32_t* r, uint32_t addr) {
    asm volatile("ldmatrix.sync.aligned.m8n8.x4.shared.b16 {%0,%1,%2,%3}, [%4];"
                 : "=r"(r[0]), "=r"(r[1]), "=r"(r[2]), "=r"(r[3]) : "r"(addr));
}

__device__ __forceinline__ void mma16816(float* c, const uint32_t* a,
                                         uint32_t b0, uint32_t b1) {
    asm volatile(
        "mma.sync.aligned.m16n8k16.row.col.f32.f16.f16.f32 "
        "{%0,%1,%2,%3}, {%4,%5,%6,%7}, {%8,%9}, {%0,%1,%2,%3};"
        : "+f"(c[0]), "+f"(c[1]), "+f"(c[2]), "+f"(c[3])
        : "r"(a[0]), "r"(a[1]), "r"(a[2]), "r"(a[3]), "r"(b0), "r"(b1));
}

// 128B-row tile, 8 granules of 16B, XOR-swizzled (verified conflict-free).
__device__ __forceinline__ uint32_t tile_off(int row, int g) {
    return (uint32_t)(row * 128 + ((g ^ (row & 7)) * 16));
}

// ---------------------------------------------------------------------------
// Prep (fused, single kernel): A-scatter+convert blocks, then W-convert.
// Scatter identity xp[invp[c]] = x[c] needs no forward-perm table:
// x reads are coalesced float4; invp is L2-hot 16KB; stores are 2B scalars
// that stay near-contiguous (invp is monotone off the 128 outlier columns).
// ---------------------------------------------------------------------------
__global__ __launch_bounds__(256)
void prep_AW_kernel(const float4* __restrict__ x4,
                    const int* __restrict__ invp,
                    const float4* __restrict__ qw4,
                    const float4* __restrict__ fw4) {
    const int b = blockIdx.x;
    if (b < GATHER_BLOCKS) {
        size_t idx = (size_t)b * 256 + threadIdx.x;        // over M*K/4
        const int m  = (int)(idx >> 10);                   // K/4 = 1024
        const int c4 = (int)(idx & 1023);
        float4 v = x4[idx];
        __half* dst = g_A + (size_t)m * K_DIM;
        const int* ip = invp + 4 * c4;
        dst[ip[0]] = __float2half_rn(v.x);
        dst[ip[1]] = __float2half_rn(v.y);
        dst[ip[2]] = __float2half_rn(v.z);
        dst[ip[3]] = __float2half_rn(v.w);
    } else {
        size_t idx = (size_t)(b - GATHER_BLOCKS) * 256 + threadIdx.x;
        const size_t nq4 = (size_t)N_DIM * KQ_DIM / 4;
        float4 v;
        __half2* dst;
        if (idx < nq4) { v = qw4[idx]; dst = (__half2*)(g_Q + 4 * idx); }
        else { v = fw4[idx - nq4]; dst = (__half2*)(g_FP + 4 * (idx - nq4)); }
        dst[0] = __floats2half2_rn(v.x, v.y);
        dst[1] = __floats2half2_rn(v.z, v.w);
    }
}

// ---------------------------------------------------------------------------
// GEMM (R15, unchanged): acc = xp[:, :3968]*q^T ; acc *= alpha[n] ;
// acc += outliers ; C = acc + bias.
// CTA 128x128, 256 threads / 8 warps (2m x 4n), warp tile 64x32, KC=64,
// 3-stage cp.async pipeline, 2 CTAs/SM. Hot loop unrolled by the stage
// period (3) so every smem offset is a compile-time immediate.
// ---------------------------------------------------------------------------
__global__ __launch_bounds__(256, 2)
void gemm_hmma_kernel(const float* __restrict__ alpha,
                      const float* __restrict__ bias,
                      float* __restrict__ C) {
    extern __shared__ char smem[];
    const uint32_t sbase = smem_to_u32(smem);
    const int tid = threadIdx.x;
    const int wid = tid >> 5;
    const int lid = tid & 31;
    const int wm  = wid >> 2;          // 0..1 -> m offset wm*64
    const int wn  = wid & 3;           // 0..3 -> n offset wn*32
    const int m0  = blockIdx.y * TM;
    const int n0  = blockIdx.x * TN;

    float acc[4][4][4];                // [m16][n8][quad] = 64 regs
    #pragma unroll
    for (int i = 0; i < 4; i++)
        #pragma unroll
        for (int j = 0; j < 4; j++)
            #pragma unroll
            for (int t = 0; t < 4; t++) acc[i][j][t] = 0.0f;

    // ---- loader: walking pointers, 8 cp.async x 16B per thread ----
    const int lrow = tid >> 3;          // 0..31
    const int lg   = tid & 7;           // 16B granule within 128B row
    const __half* pA = g_A  + (size_t)(m0 + lrow) * K_DIM  + lg * 8;
    const __half* pQ = g_Q  + (size_t)(n0 + lrow) * KQ_DIM + lg * 8;
    const __half* pF = g_FP + (size_t)(n0 + lrow) * N_OUTL + lg * 8;
    const uint32_t dA = sbase + OFF_A + tile_off(lrow, lg);
    const uint32_t dB = sbase + OFF_B + tile_off(lrow, lg);

    auto load_q = [&](uint32_t so) {    // straight-line, no branches
        #pragma unroll
        for (int p = 0; p < 4; p++)     // A: 128 rows (row-group stride 32)
            cpa16(dA + so + p * 4096u, pA + (size_t)p * (32 * K_DIM));
        #pragma unroll
        for (int p = 0; p < 4; p++)     // B: exact int weights
            cpa16(dB + so + p * 4096u, pQ + (size_t)p * (32 * KQ_DIM));
        pA += KC; pQ += KC;
    };
    auto load_fp = [&](uint32_t so, int t) {
        const __half* f = pF + t * KC;
        #pragma unroll
        for (int p = 0; p < 4; p++)
            cpa16(dA + so + p * 4096u, pA + (size_t)p * (32 * K_DIM));
        #pragma unroll
        for (int p = 0; p < 4; p++)
            cpa16(dB + so + p * 4096u, f + (size_t)p * (32 * N_OUTL));
        pA += KC;
    };

    // ---- fragment addressing ----
    const int frow = lid & 15;
    const int fg   = lid >> 4;
    const uint32_t r7 = (uint32_t)(frow & 7);
    uint32_t aoff[4], boff[2];
    #pragma unroll
    for (int i = 0; i < 4; i++)
        aoff[i] = sbase + OFF_A + (uint32_t)(wm * 64 + i * 16 + frow) * 128;
    #pragma unroll
    for (int j = 0; j < 2; j++)
        boff[j] = sbase + OFF_B + (uint32_t)(wn * 32 + j * 16 + frow) * 128;

    // per stage: 4 k16 s-steps; per s-step 6 LDSM + 16 independent MMAs
    auto compute_stage = [&](uint32_t so) {
        #pragma unroll
        for (int s = 0; s < 4; s++) {
            const uint32_t sw = so + ((((uint32_t)(2 * s + fg)) ^ r7) << 4);
            uint32_t a[4][4], b[2][4];
            #pragma unroll
            for (int j = 0; j < 2; j++) ldsm4(b[j], boff[j] + sw);
            #pragma unroll
            for (int i = 0; i < 4; i++) ldsm4(a[i], aoff[i] + sw);
            #pragma unroll
            for (int i = 0; i < 4; i++)
                #pragma unroll
                for (int j = 0; j < 2; j++) {
                    mma16816(acc[i][2 * j],     a[i], b[j][0], b[j][2]);
                    mma16816(acc[i][2 * j + 1], a[i], b[j][1], b[j][3]);
                }
        }
    };

    const int tq = lid & 3;

#define WAIT1() asm volatile("cp.async.wait_group 1;" ::: "memory")
#define WAIT0() asm volatile("cp.async.wait_group 0;" ::: "memory")
#define COMMIT() asm volatile("cp.async.commit_group;" ::: "memory")
#define HOT_ITER(CUR, NXT) do { \
        WAIT1(); __syncthreads();  \
        load_q(NXT); COMMIT();     \
        compute_stage(CUR);        \
    } while (0)

    // ---- prologue: tiles 0,1 (both Q) -> slots 0,1 ----
    load_q(0 * STAGE_BYTES); COMMIT();
    load_q(1 * STAGE_BYTES); COMMIT();

    // ---- hot loop: 60 iters = 20 x stage period; all offsets immediate ----
    #pragma unroll 1
    for (int c = 0; c < (NQ_IT - 2) / 3; c++) {
        HOT_ITER(0 * STAGE_BYTES, 2 * STAGE_BYTES);   // kt=3c+0
        HOT_ITER(1 * STAGE_BYTES, 0 * STAGE_BYTES);   // kt=3c+1
        HOT_ITER(2 * STAGE_BYTES, 1 * STAGE_BYTES);   // kt=3c+2
    }

    // ---- transition: kt=60,61 prefetch FP tiles 62,63 (slots 2,0) ----
    WAIT1(); __syncthreads();
    load_fp(2 * STAGE_BYTES, 0); COMMIT();
    compute_stage(0 * STAGE_BYTES);                   // tile 60
    WAIT1(); __syncthreads();
    load_fp(0 * STAGE_BYTES, 1); COMMIT();
    compute_stage(1 * STAGE_BYTES);                   // tile 61

    // ---- q-part complete: per-output-column alpha on accumulators ----
    #pragma unroll
    for (int j2 = 0; j2 < 4; j2++) {
        const int nc = n0 + wn * 32 + j2 * 8 + 2 * tq;
        const float s0 = alpha[nc], s1 = alpha[nc + 1];
        #pragma unroll
        for (int i = 0; i < 4; i++) {
            acc[i][j2][0] *= s0; acc[i][j2][1] *= s1;
            acc[i][j2][2] *= s0; acc[i][j2][3] *= s1;
        }
    }

    // ---- tail: tiles 62 (slot 2), 63 (slot 0); no further loads ----
    WAIT1(); __syncthreads();
    compute_stage(2 * STAGE_BYTES);
    WAIT0(); __syncthreads();
    compute_stage(0 * STAGE_BYTES);

#undef HOT_ITER
#undef WAIT1
#undef WAIT0
#undef COMMIT

    // ---- epilogue: bias + float2 stores ----
    const int qid = lid >> 2;
    #pragma unroll
    for (int i = 0; i < 4; i++) {
        const int mrow = m0 + wm * 64 + i * 16 + qid;
        #pragma unroll
        for (int j2 = 0; j2 < 4; j2++) {
            const int nc = n0 + wn * 32 + j2 * 8 + 2 * tq;
            const float b0 = bias[nc], b1 = bias[nc + 1];
            float2 v0 = make_float2(acc[i][j2][0] + b0, acc[i][j2][1] + b1);
            float2 v1 = make_float2(acc[i][j2][2] + b0, acc[i][j2][3] + b1);
            *(float2*)&C[(size_t)mrow * N_DIM + nc]       = v0;
            *(float2*)&C[(size_t)(mrow + 8) * N_DIM + nc] = v1;
        }
    }
}

// ---------------------------------------------------------------------------
// Launch. Inputs: input, q_weight, fp_weight, alpha_scale, bias, inv_col_perm.
// ---------------------------------------------------------------------------
extern "C" void kernel_launch(void* const* d_in, const int* in_sizes, int n_in,
                              void* d_out, int out_size) {
    const float* input = (const float*)d_in[0];
    const float* qw    = (const float*)d_in[1];
    const float* fw    = (const float*)d_in[2];
    const float* alpha = (const float*)d_in[3];
    const float* bias  = (const float*)d_in[4];
    const int*   invp  = (const int*)  d_in[5];
    float* out = (float*)d_out;

    prep_AW_kernel<<<GATHER_BLOCKS + W_BLOCKS, 256>>>(
        (const float4*)input, invp, (const float4*)qw, (const float4*)fw);

    static bool attr_set = false;
    if (!attr_set) {
        cudaFuncSetAttribute(gemm_hmma_kernel,
                             cudaFuncAttributeMaxDynamicSharedMemorySize, SMEM_TOTAL);
        attr_set = true;
    }
    dim3 grid(N_DIM / TN, M_ROWS / TM);   // (32, 64) = 2048 CTAs
    gemm_hmma_kernel<<<grid, 256, SMEM_TOTAL>>>(alpha, bias, out);
}